// round 15
// baseline (speedup 1.0000x reference)
#include <cuda_runtime.h>
#include <math.h>

// DifferentiableNERF, round 15.
// R14's intra-thread ILP2 chain split (two independent 6-atom chains per
// thread, stitched by rigid equivariance: P = PA o PB, chain-B world
// transform WB = W o PA) — which measured +7% per-warp — combined with
// R13's occupancy 7 by PARKING PA IN SHARED MEMORY during the scan:
// PA is cold across the 5-level Kogge-Stone; storing its 12 floats to a
// padded smem slot ([128][13], stride 13 -> conflict-free) frees ~12
// registers at the pressure peak so the kernel fits the 73-reg cap of
// __launch_bounds__(128, 7) without spills.

namespace {

constexpr int L_CONST = 512;
constexpr int NSTEP = L_CONST - 1;   // 511
constexpr int SEG = 4;               // steps per thread
constexpr int THREADS = 128;         // 4 warps = 1 chain
constexpr int CHAIN_FLOATS = 3 * L_CONST * 3;  // 4608
constexpr int ROWS = SEG * 9;        // 36
constexpr int COLS = THREADS + 1;    // 129 (conflict-free stride)
constexpr int WRAP = ROWS * COLS - 1;          // 4643
constexpr int STEP_PTR = 8 * COLS + 14;        // 1046 (g += 512)

struct FC { float ex[3]; float ey[3]; float ez[3]; float t[3]; };

struct V3 { float x, y, z; };

__device__ __forceinline__ V3 vcross(V3 a, V3 b) {
    return { a.y * b.z - a.z * b.y,
             a.z * b.x - a.x * b.z,
             a.x * b.y - a.y * b.x };
}
__device__ __forceinline__ float vdot(V3 a, V3 b) { return a.x * b.x + a.y * b.y + a.z * b.z; }
__device__ __forceinline__ V3 vunit(V3 a) {
    float r = rsqrtf(fmaxf(vdot(a, a), 1e-30f));
    return { a.x * r, a.y * r, a.z * r };
}

struct Aff { float m[9]; float t[3]; };

__device__ __forceinline__ Aff identityAff() {
    Aff r;
    r.m[0] = 1.f; r.m[1] = 0.f; r.m[2] = 0.f;
    r.m[3] = 0.f; r.m[4] = 1.f; r.m[5] = 0.f;
    r.m[6] = 0.f; r.m[7] = 0.f; r.m[8] = 1.f;
    r.t[0] = 0.f; r.t[1] = 0.f; r.t[2] = 0.f;
    return r;
}

// (A o B)(x) = A(B(x))
__device__ __forceinline__ Aff compose(const Aff& A, const Aff& B) {
    Aff r;
#pragma unroll
    for (int i = 0; i < 3; i++) {
#pragma unroll
        for (int j = 0; j < 3; j++) {
            r.m[3 * i + j] = A.m[3 * i + 0] * B.m[0 + j]
                           + A.m[3 * i + 1] * B.m[3 + j]
                           + A.m[3 * i + 2] * B.m[6 + j];
        }
        r.t[i] = A.m[3 * i + 0] * B.t[0]
               + A.m[3 * i + 1] * B.t[1]
               + A.m[3 * i + 2] * B.t[2] + A.t[i];
    }
    return r;
}

// Orthonormal placement frame: ex = bond dir, ez = plane normal, ey = ez x ex.
struct Frame { V3 ex, ey, ez; V3 c; };

__device__ __forceinline__ V3 placeF(Frame& F, float ang, float len, float tor) {
    float st, ct, sa, ca;
    __sincosf(tor, &st, &ct);
    __sincosf(ang, &sa, &ca);
    float k2 = ct * sa, k3 = st * sa;
    V3 u  = { k3 * F.ez.x + (k2 * F.ey.x - ca * F.ex.x),
              k3 * F.ez.y + (k2 * F.ey.y - ca * F.ex.y),
              k3 * F.ez.z + (k2 * F.ey.z - ca * F.ex.z) };
    V3 p  = { F.c.x + len * u.x, F.c.y + len * u.y, F.c.z + len * u.z };
    V3 ez2 = { ct * F.ez.x - st * F.ey.x,
               ct * F.ez.y - st * F.ey.y,
               ct * F.ez.z - st * F.ey.z };
    V3 ey2 = vcross(ez2, u);
    F.ex = u; F.ey = ey2; F.ez = ez2; F.c = p;
    return p;
}

// Gram-Schmidt: restore exact orthonormality of the propagated frame.
__device__ __forceinline__ void orthonormalize(Frame& F) {
    V3 ex = vunit(F.ex);
    float d = vdot(F.ez, ex);
    V3 ez = { F.ez.x - d * ex.x, F.ez.y - d * ex.y, F.ez.z - d * ex.z };
    ez = vunit(ez);
    F.ex = ex;
    F.ez = ez;
    F.ey = vcross(ez, ex);
}

__device__ __forceinline__ Aff frameToAff(const Frame& F) {
    Aff A;
    A.m[0] = F.ex.x; A.m[1] = F.ey.x; A.m[2] = F.ez.x;
    A.m[3] = F.ex.y; A.m[4] = F.ey.y; A.m[5] = F.ez.y;
    A.m[6] = F.ex.z; A.m[7] = F.ey.z; A.m[8] = F.ez.z;
    A.t[0] = F.c.x;  A.t[1] = F.c.y;  A.t[2] = F.c.z;
    return A;
}

__device__ __forceinline__ Aff shflUpAff(const Aff& A, int delta) {
    Aff r;
#pragma unroll
    for (int k = 0; k < 9; k++) r.m[k] = __shfl_up_sync(0xffffffffu, A.m[k], delta);
#pragma unroll
    for (int k = 0; k < 3; k++) r.t[k] = __shfl_up_sync(0xffffffffu, A.t[k], delta);
    return r;
}

__constant__ float c9[12] = {
    17.047f, 14.099f, 3.625f,
    16.967f, 12.784f, 4.338f,
    15.685f, 12.755f, 5.133f,
    0.f, 0.f, 0.f
};

__global__ __launch_bounds__(THREADS, 7)
void nerf_kernel(const float* __restrict__ phi,
                 const float* __restrict__ psi,
                 const float* __restrict__ omega,
                 const float* __restrict__ bl,
                 const float* __restrict__ ba,
                 float* __restrict__ out,
                 const FC fc) {
    __shared__ float traj[ROWS][COLS];
    __shared__ float warpTot[3][12];     // inclusive totals of warps 0..2
    __shared__ float paS[THREADS][13];   // PA parked during scan (stride 13: conflict-free)

    const int tid  = threadIdx.x;
    const int lane = tid & 31;
    const int warp = tid >> 5;
    const int chain = blockIdx.x;

    const int base = tid * SEG;

    const float* __restrict__ phiR = phi   + (size_t)chain * L_CONST;
    const float* __restrict__ psiS = psi   + (size_t)chain * L_CONST + base;
    const float* __restrict__ omgS = omega + (size_t)chain * L_CONST + base;
    const float* __restrict__ blS  = bl + (size_t)chain * L_CONST * 3 + 3 * base;
    const float* __restrict__ baS  = ba + (size_t)chain * L_CONST * 3 + 3 * base;

    // ---- Batched vector loads of this thread's 4-step inputs ----
    float4 psq = *(const float4*)psiS;
    float4 omq = *(const float4*)omgS;
    float4 blq[3], baq[3];
#pragma unroll
    for (int q = 0; q < 3; q++) {
        blq[q] = *(const float4*)(blS + 4 * q);
        baq[q] = *(const float4*)(baS + 4 * q);
    }
    float4 phq = *(const float4*)(phiR + base);   // phi[base .. base+3]
    float ph3 = __shfl_down_sync(0xffffffffu, phq.x, 1);   // phi[base+4]
    if (lane == 31) {
        int ip = base + SEG;
        if (ip > NSTEP) ip = NSTEP;   // in-bounds; value only reaches a dead row
        ph3 = phiR[ip];
    }
    float phv[4] = { phq.y, phq.z, phq.w, ph3 };
    const float* psf = (const float*)&psq;
    const float* omf = (const float*)&omq;
    const float* blf = (const float*)blq;
    const float* baf = (const float*)baq;

    // ---- Pass 1: TWO independent 6-atom chains from the canonical frame ----
    Frame FrA, FrB;
    FrA.ex = { fc.ex[0], fc.ex[1], fc.ex[2] };
    FrA.ey = { fc.ey[0], fc.ey[1], fc.ey[2] };
    FrA.ez = { fc.ez[0], fc.ez[1], fc.ez[2] };
    FrA.c  = { 15.685f, 12.755f, 5.133f };
    FrB = FrA;

#pragma unroll
    for (int h = 0; h < 2; h++) {
        // Chain A: global step t = h
        {
            int t = h;
            V3 p1 = placeF(FrA, baf[3 * t + 1], blf[3 * t + 2], psf[t]);
            V3 p2 = placeF(FrA, baf[3 * t + 2], blf[3 * t + 0], omf[t]);
            V3 p3 = placeF(FrA, baf[3 * t + 0], blf[3 * t + 1], phv[t]);
            traj[9 * t + 0][tid] = p1.x; traj[9 * t + 1][tid] = p1.y; traj[9 * t + 2][tid] = p1.z;
            traj[9 * t + 3][tid] = p2.x; traj[9 * t + 4][tid] = p2.y; traj[9 * t + 5][tid] = p2.z;
            traj[9 * t + 6][tid] = p3.x; traj[9 * t + 7][tid] = p3.y; traj[9 * t + 8][tid] = p3.z;
        }
        // Chain B: global step t = h + 2 (unguarded: only thread 127's t=3
        // is past NSTEP; its traj rows 27..35 are dead, its P feeds no one)
        {
            int t = h + 2;
            V3 p1 = placeF(FrB, baf[3 * t + 1], blf[3 * t + 2], psf[t]);
            V3 p2 = placeF(FrB, baf[3 * t + 2], blf[3 * t + 0], omf[t]);
            V3 p3 = placeF(FrB, baf[3 * t + 0], blf[3 * t + 1], phv[t]);
            traj[9 * t + 0][tid] = p1.x; traj[9 * t + 1][tid] = p1.y; traj[9 * t + 2][tid] = p1.z;
            traj[9 * t + 3][tid] = p2.x; traj[9 * t + 4][tid] = p2.y; traj[9 * t + 5][tid] = p2.z;
            traj[9 * t + 6][tid] = p3.x; traj[9 * t + 7][tid] = p3.y; traj[9 * t + 8][tid] = p3.z;
        }
    }

    // GS both half-endpoints (6-atom drift windows; scan inputs must be
    // exact rotations, R6/R8 lesson).
    orthonormalize(FrA);
    orthonormalize(FrB);

    // ---- Conjugated transforms: PA = F(EA) o F0^-1, PB = F(EB) o F0^-1 ----
    Aff F0i;
    F0i.m[0] = fc.ex[0]; F0i.m[1] = fc.ex[1]; F0i.m[2] = fc.ex[2];
    F0i.m[3] = fc.ey[0]; F0i.m[4] = fc.ey[1]; F0i.m[5] = fc.ey[2];
    F0i.m[6] = fc.ez[0]; F0i.m[7] = fc.ez[1]; F0i.m[8] = fc.ez[2];
    F0i.t[0] = fc.t[0];  F0i.t[1] = fc.t[1];  F0i.t[2] = fc.t[2];

    Aff P;
    {
        Aff PA = compose(frameToAff(FrA), F0i);
        Aff PB = compose(frameToAff(FrB), F0i);
        // Park PA in smem: cold during the scan, frees ~12 registers at the
        // pressure peak (the reason R14 fell to 6 blocks/SM).
#pragma unroll
        for (int k = 0; k < 9; k++) paS[tid][k] = PA.m[k];
#pragma unroll
        for (int k = 0; k < 3; k++) paS[tid][9 + k] = PA.t[k];
        P = compose(PA, PB);   // full segment transform (equivariance)
    }

    // Warp inclusive Kogge-Stone scan
#pragma unroll
    for (int off = 1; off < 32; off <<= 1) {
        Aff prev = shflUpAff(P, off);
        Aff comb = compose(prev, P);
        if (lane >= off) P = comb;
    }

    // Publish warp totals
    if (lane == 31 && warp < 3) {
#pragma unroll
        for (int k = 0; k < 9; k++) warpTot[warp][k] = P.m[k];
#pragma unroll
        for (int k = 0; k < 3; k++) warpTot[warp][9 + k] = P.t[k];
    }

    Aff Pex = shflUpAff(P, 1);   // warp-local exclusive prefix
    __syncthreads();

    // W = warpTot[0] o ... o warpTot[warp-1] o Pex   (exclusive prefix = W)
    Aff W = (lane == 0) ? identityAff() : Pex;
    for (int v = warp - 1; v >= 0; v--) {
        Aff T;
#pragma unroll
        for (int k = 0; k < 9; k++) T.m[k] = warpTot[v][k];
#pragma unroll
        for (int k = 0; k < 3; k++) T.t[k] = warpTot[v][9 + k];
        W = compose(T, W);
    }

    // Chain-B rows are in second-half-local coords: world = W o PA o local.
    Aff WB;
    {
        Aff PA;
#pragma unroll
        for (int k = 0; k < 9; k++) PA.m[k] = paS[tid][k];
#pragma unroll
        for (int k = 0; k < 3; k++) PA.t[k] = paS[tid][9 + k];
        WB = compose(W, PA);
    }

    // ---- Pass 2: transform local trajectory in SMEM ----
#pragma unroll
    for (int s = 0; s < SEG; s++) {
        const Aff& T = (s < 2) ? W : WB;
#pragma unroll
        for (int p = 0; p < 3; p++) {
            V3 v;
            v.x = traj[9 * s + 3 * p + 0][tid];
            v.y = traj[9 * s + 3 * p + 1][tid];
            v.z = traj[9 * s + 3 * p + 2][tid];
            float wx = T.m[0] * v.x + T.m[1] * v.y + T.m[2] * v.z + T.t[0];
            float wy = T.m[3] * v.x + T.m[4] * v.y + T.m[5] * v.z + T.t[1];
            float wz = T.m[6] * v.x + T.m[7] * v.y + T.m[8] * v.z + T.t[2];
            traj[9 * s + 3 * p + 0][tid] = wx;
            traj[9 * s + 3 * p + 1][tid] = wy;
            traj[9 * s + 3 * p + 2][tid] = wz;
        }
    }
    __syncthreads();

    // ---- Writeout: float4 groups, division-free group walk (R13) ----
    float* __restrict__ outC = out + (size_t)chain * CHAIN_FLOATS;
    float4* __restrict__ outV = (float4*)outC;
    const float* trajF = &traj[0][0];

    // Iteration 0.
    if (tid < 3) {
#pragma unroll
        for (int w = 0; w < 4; w++) {
            int f = 4 * tid + w;
            outC[f] = (f < 9) ? c9[f] : trajF[(f - 9) * COLS];
        }
    } else {
        int g0 = 4 * tid - 9;
        int ow0 = g0 / 36;
        int rw0 = g0 - 36 * ow0;
        const float* p0 = trajF + rw0 * COLS + ow0;
        float vv[4];
#pragma unroll
        for (int w = 0; w < 4; w++) {
            const float* a = p0 + w * COLS;
            if (rw0 + w >= ROWS) a -= WRAP;
            vv[w] = *a;
        }
        outV[tid] = make_float4(vv[0], vv[1], vv[2], vv[3]);
    }

    // Iterations 1..8: state computed directly for g1 = 503 + 4*tid.
    int g1 = 503 + 4 * tid;
    int ow = g1 / 36;
    int rw = g1 - 36 * ow;
    const float* p = trajF + rw * COLS + ow;
#pragma unroll
    for (int it = 1; it < 9; it++) {
        float vv[4];
#pragma unroll
        for (int w = 0; w < 4; w++) {
            const float* a = p + w * COLS;
            if (rw + w >= ROWS) a -= WRAP;
            vv[w] = *a;
        }
        outV[it * THREADS + tid] = make_float4(vv[0], vv[1], vv[2], vv[3]);
        rw += 8;
        p += STEP_PTR;
        if (rw >= ROWS) { rw -= ROWS; p -= WRAP; }
    }
}

} // anonymous namespace

extern "C" void kernel_launch(void* const* d_in, const int* in_sizes, int n_in,
                              void* d_out, int out_size) {
    const float* phi   = (const float*)d_in[0];
    const float* psi   = (const float*)d_in[1];
    const float* omega = (const float*)d_in[2];
    const float* bl    = (const float*)d_in[3];
    const float* ba    = (const float*)d_in[4];

    const int B = in_sizes[0] / L_CONST;

    // Canonical frame of (A0, B0, C0) in double precision.
    const double A0[3] = {17.047, 14.099, 3.625};
    const double B0[3] = {16.967, 12.784, 4.338};
    const double C0[3] = {15.685, 12.755, 5.133};
    double ex[3], ab[3], ez[3], ey[3];
    for (int i = 0; i < 3; i++) { ex[i] = C0[i] - B0[i]; ab[i] = B0[i] - A0[i]; }
    double n = sqrt(ex[0]*ex[0] + ex[1]*ex[1] + ex[2]*ex[2]);
    for (int i = 0; i < 3; i++) ex[i] /= n;
    ez[0] = ab[1]*ex[2] - ab[2]*ex[1];
    ez[1] = ab[2]*ex[0] - ab[0]*ex[2];
    ez[2] = ab[0]*ex[1] - ab[1]*ex[0];
    n = sqrt(ez[0]*ez[0] + ez[1]*ez[1] + ez[2]*ez[2]);
    for (int i = 0; i < 3; i++) ez[i] /= n;
    ey[0] = ez[1]*ex[2] - ez[2]*ex[1];
    ey[1] = ez[2]*ex[0] - ez[0]*ex[2];
    ey[2] = ez[0]*ex[1] - ez[1]*ex[0];

    FC fc;
    for (int i = 0; i < 3; i++) {
        fc.ex[i] = (float)ex[i];
        fc.ey[i] = (float)ey[i];
        fc.ez[i] = (float)ez[i];
    }
    fc.t[0] = (float)(-(ex[0]*C0[0] + ex[1]*C0[1] + ex[2]*C0[2]));
    fc.t[1] = (float)(-(ey[0]*C0[0] + ey[1]*C0[1] + ey[2]*C0[2]));
    fc.t[2] = (float)(-(ez[0]*C0[0] + ez[1]*C0[1] + ez[2]*C0[2]));

    nerf_kernel<<<B, THREADS>>>(phi, psi, omega, bl, ba, (float*)d_out, fc);
}

// round 16
// speedup vs baseline: 1.1152x; 1.1152x over previous
#include <cuda_runtime.h>
#include <math.h>

// DifferentiableNERF, round 16 — consolidation of the R13 optimum.
// SEG=4, 128 threads/chain, transposed conflict-free SMEM traj[36][129],
// closed-form frame propagation + end-of-segment Gram-Schmidt, matrix
// Kogge-Stone scan in conjugated space, host-computed F0 constants,
// unguarded pass 1, float4-group division-free writeout.
// R14/R15 post-mortem: ILP2 splits and register-cap forcing all lost to
// register-allocator economics (spills / occupancy). This keeps R13's
// natural 72-reg configuration; pass 2 is re-expressed as a linear row
// walk (rows 0..35 sequential per column -> single pointer increment).

namespace {

constexpr int L_CONST = 512;
constexpr int NSTEP = L_CONST - 1;   // 511
constexpr int SEG = 4;               // steps per thread
constexpr int THREADS = 128;         // 4 warps = 1 chain
constexpr int CHAIN_FLOATS = 3 * L_CONST * 3;  // 4608
constexpr int ROWS = SEG * 9;        // 36
constexpr int COLS = THREADS + 1;    // 129 (conflict-free stride)
constexpr int WRAP = ROWS * COLS - 1;          // 4643
constexpr int STEP_PTR = 8 * COLS + 14;        // 1046 (g += 512)

struct FC { float ex[3]; float ey[3]; float ez[3]; float t[3]; };

struct V3 { float x, y, z; };

__device__ __forceinline__ V3 vcross(V3 a, V3 b) {
    return { a.y * b.z - a.z * b.y,
             a.z * b.x - a.x * b.z,
             a.x * b.y - a.y * b.x };
}
__device__ __forceinline__ float vdot(V3 a, V3 b) { return a.x * b.x + a.y * b.y + a.z * b.z; }
__device__ __forceinline__ V3 vunit(V3 a) {
    float r = rsqrtf(fmaxf(vdot(a, a), 1e-30f));
    return { a.x * r, a.y * r, a.z * r };
}

struct Aff { float m[9]; float t[3]; };

__device__ __forceinline__ Aff identityAff() {
    Aff r;
    r.m[0] = 1.f; r.m[1] = 0.f; r.m[2] = 0.f;
    r.m[3] = 0.f; r.m[4] = 1.f; r.m[5] = 0.f;
    r.m[6] = 0.f; r.m[7] = 0.f; r.m[8] = 1.f;
    r.t[0] = 0.f; r.t[1] = 0.f; r.t[2] = 0.f;
    return r;
}

// (A o B)(x) = A(B(x))
__device__ __forceinline__ Aff compose(const Aff& A, const Aff& B) {
    Aff r;
#pragma unroll
    for (int i = 0; i < 3; i++) {
#pragma unroll
        for (int j = 0; j < 3; j++) {
            r.m[3 * i + j] = A.m[3 * i + 0] * B.m[0 + j]
                           + A.m[3 * i + 1] * B.m[3 + j]
                           + A.m[3 * i + 2] * B.m[6 + j];
        }
        r.t[i] = A.m[3 * i + 0] * B.t[0]
               + A.m[3 * i + 1] * B.t[1]
               + A.m[3 * i + 2] * B.t[2] + A.t[i];
    }
    return r;
}

// Orthonormal placement frame: ex = bond dir, ez = plane normal, ey = ez x ex.
struct Frame { V3 ex, ey, ez; V3 c; };

__device__ __forceinline__ V3 placeF(Frame& F, float ang, float len, float tor) {
    float st, ct, sa, ca;
    __sincosf(tor, &st, &ct);
    __sincosf(ang, &sa, &ca);
    float k2 = ct * sa, k3 = st * sa;
    V3 u  = { k3 * F.ez.x + (k2 * F.ey.x - ca * F.ex.x),
              k3 * F.ez.y + (k2 * F.ey.y - ca * F.ex.y),
              k3 * F.ez.z + (k2 * F.ey.z - ca * F.ex.z) };
    V3 p  = { F.c.x + len * u.x, F.c.y + len * u.y, F.c.z + len * u.z };
    V3 ez2 = { ct * F.ez.x - st * F.ey.x,
               ct * F.ez.y - st * F.ey.y,
               ct * F.ez.z - st * F.ey.z };
    V3 ey2 = vcross(ez2, u);
    F.ex = u; F.ey = ey2; F.ez = ez2; F.c = p;
    return p;
}

// Gram-Schmidt: restore exact orthonormality of the propagated frame.
__device__ __forceinline__ void orthonormalize(Frame& F) {
    V3 ex = vunit(F.ex);
    float d = vdot(F.ez, ex);
    V3 ez = { F.ez.x - d * ex.x, F.ez.y - d * ex.y, F.ez.z - d * ex.z };
    ez = vunit(ez);
    F.ex = ex;
    F.ez = ez;
    F.ey = vcross(ez, ex);
}

__device__ __forceinline__ Aff frameToAff(const Frame& F) {
    Aff A;
    A.m[0] = F.ex.x; A.m[1] = F.ey.x; A.m[2] = F.ez.x;
    A.m[3] = F.ex.y; A.m[4] = F.ey.y; A.m[5] = F.ez.y;
    A.m[6] = F.ex.z; A.m[7] = F.ey.z; A.m[8] = F.ez.z;
    A.t[0] = F.c.x;  A.t[1] = F.c.y;  A.t[2] = F.c.z;
    return A;
}

__device__ __forceinline__ Aff shflUpAff(const Aff& A, int delta) {
    Aff r;
#pragma unroll
    for (int k = 0; k < 9; k++) r.m[k] = __shfl_up_sync(0xffffffffu, A.m[k], delta);
#pragma unroll
    for (int k = 0; k < 3; k++) r.t[k] = __shfl_up_sync(0xffffffffu, A.t[k], delta);
    return r;
}

__constant__ float c9[12] = {
    17.047f, 14.099f, 3.625f,
    16.967f, 12.784f, 4.338f,
    15.685f, 12.755f, 5.133f,
    0.f, 0.f, 0.f
};

__global__ __launch_bounds__(THREADS, 7)
void nerf_kernel(const float* __restrict__ phi,
                 const float* __restrict__ psi,
                 const float* __restrict__ omega,
                 const float* __restrict__ bl,
                 const float* __restrict__ ba,
                 float* __restrict__ out,
                 const FC fc) {
    __shared__ float traj[ROWS][COLS];
    __shared__ float warpTot[3][12];   // inclusive totals of warps 0..2

    const int tid  = threadIdx.x;
    const int lane = tid & 31;
    const int warp = tid >> 5;
    const int chain = blockIdx.x;

    const int base = tid * SEG;

    const float* __restrict__ phiR = phi   + (size_t)chain * L_CONST;
    const float* __restrict__ psiS = psi   + (size_t)chain * L_CONST + base;
    const float* __restrict__ omgS = omega + (size_t)chain * L_CONST + base;
    const float* __restrict__ blS  = bl + (size_t)chain * L_CONST * 3 + 3 * base;
    const float* __restrict__ baS  = ba + (size_t)chain * L_CONST * 3 + 3 * base;

    // ---- Batched vector loads of this thread's 4-step inputs ----
    float4 psq = *(const float4*)psiS;
    float4 omq = *(const float4*)omgS;
    float4 blq[3], baq[3];
#pragma unroll
    for (int q = 0; q < 3; q++) {
        blq[q] = *(const float4*)(blS + 4 * q);
        baq[q] = *(const float4*)(baS + 4 * q);
    }
    float4 phq = *(const float4*)(phiR + base);   // phi[base .. base+3]
    float ph3 = __shfl_down_sync(0xffffffffu, phq.x, 1);   // phi[base+4]
    if (lane == 31) {
        int ip = base + SEG;
        if (ip > NSTEP) ip = NSTEP;   // in-bounds; value only reaches a dead row
        ph3 = phiR[ip];
    }
    float phv[4] = { phq.y, phq.z, phq.w, ph3 };
    const float* psf = (const float*)&psq;
    const float* omf = (const float*)&omq;
    const float* blf = (const float*)blq;
    const float* baf = (const float*)baq;

    // ---- Pass 1: closed-form frame propagation from canonical init ----
    Frame Fr;
    Fr.ex = { fc.ex[0], fc.ex[1], fc.ex[2] };
    Fr.ey = { fc.ey[0], fc.ey[1], fc.ey[2] };
    Fr.ez = { fc.ez[0], fc.ez[1], fc.ez[2] };
    Fr.c  = { 15.685f, 12.755f, 5.133f };

#pragma unroll
    for (int t = 0; t < SEG; t++) {
        // Unguarded: only thread 127/t=3 is past NSTEP; its inputs are
        // in-bounds, its traj rows (27..35 of owner 127) are never read,
        // and its P feeds no consumer in the scan.
        V3 p1 = placeF(Fr, baf[3 * t + 1], blf[3 * t + 2], psf[t]);
        V3 p2 = placeF(Fr, baf[3 * t + 2], blf[3 * t + 0], omf[t]);
        V3 p3 = placeF(Fr, baf[3 * t + 0], blf[3 * t + 1], phv[t]);
        traj[9 * t + 0][tid] = p1.x; traj[9 * t + 1][tid] = p1.y; traj[9 * t + 2][tid] = p1.z;
        traj[9 * t + 3][tid] = p2.x; traj[9 * t + 4][tid] = p2.y; traj[9 * t + 5][tid] = p2.z;
        traj[9 * t + 6][tid] = p3.x; traj[9 * t + 7][tid] = p3.y; traj[9 * t + 8][tid] = p3.z;
    }

    // Scan inputs must be exact rotations (R6/R8 lesson): GS the endpoint.
    orthonormalize(Fr);

    // ---- Conjugated segment transform: H' = F(end) o F0^-1 ----
    Aff F0i;
    F0i.m[0] = fc.ex[0]; F0i.m[1] = fc.ex[1]; F0i.m[2] = fc.ex[2];
    F0i.m[3] = fc.ey[0]; F0i.m[4] = fc.ey[1]; F0i.m[5] = fc.ey[2];
    F0i.m[6] = fc.ez[0]; F0i.m[7] = fc.ez[1]; F0i.m[8] = fc.ez[2];
    F0i.t[0] = fc.t[0];  F0i.t[1] = fc.t[1];  F0i.t[2] = fc.t[2];

    Aff P = compose(frameToAff(Fr), F0i);

    // Warp inclusive Kogge-Stone scan
#pragma unroll
    for (int off = 1; off < 32; off <<= 1) {
        Aff prev = shflUpAff(P, off);
        Aff comb = compose(prev, P);
        if (lane >= off) P = comb;
    }

    // Publish warp totals
    if (lane == 31 && warp < 3) {
#pragma unroll
        for (int k = 0; k < 9; k++) warpTot[warp][k] = P.m[k];
#pragma unroll
        for (int k = 0; k < 3; k++) warpTot[warp][9 + k] = P.t[k];
    }

    Aff Pex = shflUpAff(P, 1);   // warp-local exclusive prefix
    __syncthreads();

    // W = warpTot[0] o ... o warpTot[warp-1] o Pex   (exclusive prefix = W)
    Aff W = (lane == 0) ? identityAff() : Pex;
    for (int v = warp - 1; v >= 0; v--) {
        Aff T;
#pragma unroll
        for (int k = 0; k < 9; k++) T.m[k] = warpTot[v][k];
#pragma unroll
        for (int k = 0; k < 3; k++) T.t[k] = warpTot[v][9 + k];
        W = compose(T, W);
    }

    // ---- Pass 2: transform local trajectory (linear row walk) ----
    // Rows 0..35 of column tid are visited sequentially: one pointer,
    // += COLS per row; identical math and memory pattern to R13.
    {
        float* col = &traj[0][tid];
#pragma unroll
        for (int pt = 0; pt < 12; pt++) {
            float x = col[0], y = col[COLS], z = col[2 * COLS];
            col[0]        = W.m[0] * x + W.m[1] * y + W.m[2] * z + W.t[0];
            col[COLS]     = W.m[3] * x + W.m[4] * y + W.m[5] * z + W.t[1];
            col[2 * COLS] = W.m[6] * x + W.m[7] * y + W.m[8] * z + W.t[2];
            col += 3 * COLS;
        }
    }
    __syncthreads();

    // ---- Writeout: float4 groups, division-free group walk ----
    // float4 index q = it*128 + tid (it = 0..8); floats f = 4q..4q+3,
    // element g = f - 9 lives at traj[g % 36][g / 36].
    // Group advance: g += 512 => ow += 14, rw += 8 (mod 36, one wrap max).
    float* __restrict__ outC = out + (size_t)chain * CHAIN_FLOATS;
    float4* __restrict__ outV = (float4*)outC;
    const float* trajF = &traj[0][0];

    // Iteration 0.
    if (tid < 3) {
        // f = 0..11: init constants (f<9) then owner 0 rows 0..2.
#pragma unroll
        for (int w = 0; w < 4; w++) {
            int f = 4 * tid + w;
            outC[f] = (f < 9) ? c9[f] : trajF[(f - 9) * COLS];
        }
    } else {
        int g0 = 4 * tid - 9;
        int ow0 = g0 / 36;
        int rw0 = g0 - 36 * ow0;
        const float* p0 = trajF + rw0 * COLS + ow0;
        float vv[4];
#pragma unroll
        for (int w = 0; w < 4; w++) {
            const float* a = p0 + w * COLS;
            if (rw0 + w >= ROWS) a -= WRAP;
            vv[w] = *a;
        }
        outV[tid] = make_float4(vv[0], vv[1], vv[2], vv[3]);
    }

    // Iterations 1..8: state computed directly for g1 = 503 + 4*tid.
    int g1 = 503 + 4 * tid;
    int ow = g1 / 36;
    int rw = g1 - 36 * ow;
    const float* p = trajF + rw * COLS + ow;
#pragma unroll
    for (int it = 1; it < 9; it++) {
        float vv[4];
#pragma unroll
        for (int w = 0; w < 4; w++) {
            const float* a = p + w * COLS;
            if (rw + w >= ROWS) a -= WRAP;
            vv[w] = *a;
        }
        outV[it * THREADS + tid] = make_float4(vv[0], vv[1], vv[2], vv[3]);
        rw += 8;
        p += STEP_PTR;
        if (rw >= ROWS) { rw -= ROWS; p -= WRAP; }
    }
}

} // anonymous namespace

extern "C" void kernel_launch(void* const* d_in, const int* in_sizes, int n_in,
                              void* d_out, int out_size) {
    const float* phi   = (const float*)d_in[0];
    const float* psi   = (const float*)d_in[1];
    const float* omega = (const float*)d_in[2];
    const float* bl    = (const float*)d_in[3];
    const float* ba    = (const float*)d_in[4];

    const int B = in_sizes[0] / L_CONST;

    // Canonical frame of (A0, B0, C0) in double precision.
    const double A0[3] = {17.047, 14.099, 3.625};
    const double B0[3] = {16.967, 12.784, 4.338};
    const double C0[3] = {15.685, 12.755, 5.133};
    double ex[3], ab[3], ez[3], ey[3];
    for (int i = 0; i < 3; i++) { ex[i] = C0[i] - B0[i]; ab[i] = B0[i] - A0[i]; }
    double n = sqrt(ex[0]*ex[0] + ex[1]*ex[1] + ex[2]*ex[2]);
    for (int i = 0; i < 3; i++) ex[i] /= n;
    ez[0] = ab[1]*ex[2] - ab[2]*ex[1];
    ez[1] = ab[2]*ex[0] - ab[0]*ex[2];
    ez[2] = ab[0]*ex[1] - ab[1]*ex[0];
    n = sqrt(ez[0]*ez[0] + ez[1]*ez[1] + ez[2]*ez[2]);
    for (int i = 0; i < 3; i++) ez[i] /= n;
    ey[0] = ez[1]*ex[2] - ez[2]*ex[1];
    ey[1] = ez[2]*ex[0] - ez[0]*ex[2];
    ey[2] = ez[0]*ex[1] - ez[1]*ex[0];

    FC fc;
    for (int i = 0; i < 3; i++) {
        fc.ex[i] = (float)ex[i];
        fc.ey[i] = (float)ey[i];
        fc.ez[i] = (float)ez[i];
    }
    fc.t[0] = (float)(-(ex[0]*C0[0] + ex[1]*C0[1] + ex[2]*C0[2]));
    fc.t[1] = (float)(-(ey[0]*C0[0] + ey[1]*C0[1] + ey[2]*C0[2]));
    fc.t[2] = (float)(-(ez[0]*C0[0] + ez[1]*C0[1] + ez[2]*C0[2]));

    nerf_kernel<<<B, THREADS>>>(phi, psi, omega, bl, ba, (float*)d_out, fc);
}

// round 17
// speedup vs baseline: 1.1811x; 1.0591x over previous
#include <cuda_runtime.h>
#include <math.h>

// DifferentiableNERF — FINAL (R13 configuration, verified best: 33.2us wall /
// 30.2us ncu, rel_err 3.43e-5).
//
// Design (converged over 16 rounds):
// - One 128-thread block per chain; thread owns SEG=4 residues (12 atoms).
// - Pass 1: closed-form orthonormal-frame propagation (sincos + ~26 FMA per
//   atom, no normalization) from the canonical init frame; positions stored
//   to transposed conflict-free SMEM traj[36][129].
// - Gram-Schmidt on the segment-end frame (12-atom drift window, validated:
//   without it the fast-sincos scale defect grows ~1.4x/atom and the 128-fold
//   scan composition amplifies it past 1e-3).
// - Conjugated-space segment transform P = F(end) o F0^-1 (F0 constants
//   computed on the host in double precision; F0^-1 rotation = F0 axes).
// - Warp Kogge-Stone scan of rigid affines + 4-warp combine via smem
//   => exclusive prefix = per-thread world transform W directly.
// - Pass 2: apply W in SMEM; writeout as 9x STG.128 per thread with a
//   division-free (ow += 14, rw += 8 mod 36) group walk.
//
// Mapped-out dead ends (kept for the record): SEG=8 (serial-latency loss),
// register-cap occupancy forcing (MIO/spills), ILP2 splits (allocator
// economics), owner-major vectorized SMEM (bank conflicts).

namespace {

constexpr int L_CONST = 512;
constexpr int NSTEP = L_CONST - 1;   // 511
constexpr int SEG = 4;               // steps per thread
constexpr int THREADS = 128;         // 4 warps = 1 chain
constexpr int CHAIN_FLOATS = 3 * L_CONST * 3;  // 4608
constexpr int ROWS = SEG * 9;        // 36
constexpr int COLS = THREADS + 1;    // 129 (conflict-free stride)
constexpr int WRAP = ROWS * COLS - 1;          // 4643
constexpr int STEP_PTR = 8 * COLS + 14;        // 1046 (g += 512)

struct FC { float ex[3]; float ey[3]; float ez[3]; float t[3]; };

struct V3 { float x, y, z; };

__device__ __forceinline__ V3 vcross(V3 a, V3 b) {
    return { a.y * b.z - a.z * b.y,
             a.z * b.x - a.x * b.z,
             a.x * b.y - a.y * b.x };
}
__device__ __forceinline__ float vdot(V3 a, V3 b) { return a.x * b.x + a.y * b.y + a.z * b.z; }
__device__ __forceinline__ V3 vunit(V3 a) {
    float r = rsqrtf(fmaxf(vdot(a, a), 1e-30f));
    return { a.x * r, a.y * r, a.z * r };
}

struct Aff { float m[9]; float t[3]; };

__device__ __forceinline__ Aff identityAff() {
    Aff r;
    r.m[0] = 1.f; r.m[1] = 0.f; r.m[2] = 0.f;
    r.m[3] = 0.f; r.m[4] = 1.f; r.m[5] = 0.f;
    r.m[6] = 0.f; r.m[7] = 0.f; r.m[8] = 1.f;
    r.t[0] = 0.f; r.t[1] = 0.f; r.t[2] = 0.f;
    return r;
}

// (A o B)(x) = A(B(x))
__device__ __forceinline__ Aff compose(const Aff& A, const Aff& B) {
    Aff r;
#pragma unroll
    for (int i = 0; i < 3; i++) {
#pragma unroll
        for (int j = 0; j < 3; j++) {
            r.m[3 * i + j] = A.m[3 * i + 0] * B.m[0 + j]
                           + A.m[3 * i + 1] * B.m[3 + j]
                           + A.m[3 * i + 2] * B.m[6 + j];
        }
        r.t[i] = A.m[3 * i + 0] * B.t[0]
               + A.m[3 * i + 1] * B.t[1]
               + A.m[3 * i + 2] * B.t[2] + A.t[i];
    }
    return r;
}

// Orthonormal placement frame: ex = bond dir, ez = plane normal, ey = ez x ex.
struct Frame { V3 ex, ey, ez; V3 c; };

__device__ __forceinline__ V3 placeF(Frame& F, float ang, float len, float tor) {
    float st, ct, sa, ca;
    __sincosf(tor, &st, &ct);
    __sincosf(ang, &sa, &ca);
    float k2 = ct * sa, k3 = st * sa;
    V3 u  = { k3 * F.ez.x + (k2 * F.ey.x - ca * F.ex.x),
              k3 * F.ez.y + (k2 * F.ey.y - ca * F.ex.y),
              k3 * F.ez.z + (k2 * F.ey.z - ca * F.ex.z) };
    V3 p  = { F.c.x + len * u.x, F.c.y + len * u.y, F.c.z + len * u.z };
    V3 ez2 = { ct * F.ez.x - st * F.ey.x,
               ct * F.ez.y - st * F.ey.y,
               ct * F.ez.z - st * F.ey.z };
    V3 ey2 = vcross(ez2, u);
    F.ex = u; F.ey = ey2; F.ez = ez2; F.c = p;
    return p;
}

// Gram-Schmidt: restore exact orthonormality of the propagated frame.
__device__ __forceinline__ void orthonormalize(Frame& F) {
    V3 ex = vunit(F.ex);
    float d = vdot(F.ez, ex);
    V3 ez = { F.ez.x - d * ex.x, F.ez.y - d * ex.y, F.ez.z - d * ex.z };
    ez = vunit(ez);
    F.ex = ex;
    F.ez = ez;
    F.ey = vcross(ez, ex);
}

__device__ __forceinline__ Aff frameToAff(const Frame& F) {
    Aff A;
    A.m[0] = F.ex.x; A.m[1] = F.ey.x; A.m[2] = F.ez.x;
    A.m[3] = F.ex.y; A.m[4] = F.ey.y; A.m[5] = F.ez.y;
    A.m[6] = F.ex.z; A.m[7] = F.ey.z; A.m[8] = F.ez.z;
    A.t[0] = F.c.x;  A.t[1] = F.c.y;  A.t[2] = F.c.z;
    return A;
}

__device__ __forceinline__ Aff shflUpAff(const Aff& A, int delta) {
    Aff r;
#pragma unroll
    for (int k = 0; k < 9; k++) r.m[k] = __shfl_up_sync(0xffffffffu, A.m[k], delta);
#pragma unroll
    for (int k = 0; k < 3; k++) r.t[k] = __shfl_up_sync(0xffffffffu, A.t[k], delta);
    return r;
}

__constant__ float c9[12] = {
    17.047f, 14.099f, 3.625f,
    16.967f, 12.784f, 4.338f,
    15.685f, 12.755f, 5.133f,
    0.f, 0.f, 0.f
};

__global__ __launch_bounds__(THREADS, 7)
void nerf_kernel(const float* __restrict__ phi,
                 const float* __restrict__ psi,
                 const float* __restrict__ omega,
                 const float* __restrict__ bl,
                 const float* __restrict__ ba,
                 float* __restrict__ out,
                 const FC fc) {
    __shared__ float traj[ROWS][COLS];
    __shared__ float warpTot[3][12];   // inclusive totals of warps 0..2

    const int tid  = threadIdx.x;
    const int lane = tid & 31;
    const int warp = tid >> 5;
    const int chain = blockIdx.x;

    const int base = tid * SEG;

    const float* __restrict__ phiR = phi   + (size_t)chain * L_CONST;
    const float* __restrict__ psiS = psi   + (size_t)chain * L_CONST + base;
    const float* __restrict__ omgS = omega + (size_t)chain * L_CONST + base;
    const float* __restrict__ blS  = bl + (size_t)chain * L_CONST * 3 + 3 * base;
    const float* __restrict__ baS  = ba + (size_t)chain * L_CONST * 3 + 3 * base;

    // ---- Batched vector loads of this thread's 4-step inputs ----
    float4 psq = *(const float4*)psiS;
    float4 omq = *(const float4*)omgS;
    float4 blq[3], baq[3];
#pragma unroll
    for (int q = 0; q < 3; q++) {
        blq[q] = *(const float4*)(blS + 4 * q);
        baq[q] = *(const float4*)(baS + 4 * q);
    }
    float4 phq = *(const float4*)(phiR + base);   // phi[base .. base+3]
    float ph3 = __shfl_down_sync(0xffffffffu, phq.x, 1);   // phi[base+4]
    if (lane == 31) {
        int ip = base + SEG;
        if (ip > NSTEP) ip = NSTEP;   // in-bounds; value only reaches a dead row
        ph3 = phiR[ip];
    }
    float phv[4] = { phq.y, phq.z, phq.w, ph3 };
    const float* psf = (const float*)&psq;
    const float* omf = (const float*)&omq;
    const float* blf = (const float*)blq;
    const float* baf = (const float*)baq;

    // ---- Pass 1: closed-form frame propagation from canonical init ----
    Frame Fr;
    Fr.ex = { fc.ex[0], fc.ex[1], fc.ex[2] };
    Fr.ey = { fc.ey[0], fc.ey[1], fc.ey[2] };
    Fr.ez = { fc.ez[0], fc.ez[1], fc.ez[2] };
    Fr.c  = { 15.685f, 12.755f, 5.133f };

#pragma unroll
    for (int t = 0; t < SEG; t++) {
        // Unguarded: only thread 127/t=3 is past NSTEP; its inputs are
        // in-bounds, its traj rows (27..35 of owner 127) are never read,
        // and its P feeds no consumer in the scan.
        V3 p1 = placeF(Fr, baf[3 * t + 1], blf[3 * t + 2], psf[t]);
        V3 p2 = placeF(Fr, baf[3 * t + 2], blf[3 * t + 0], omf[t]);
        V3 p3 = placeF(Fr, baf[3 * t + 0], blf[3 * t + 1], phv[t]);
        traj[9 * t + 0][tid] = p1.x; traj[9 * t + 1][tid] = p1.y; traj[9 * t + 2][tid] = p1.z;
        traj[9 * t + 3][tid] = p2.x; traj[9 * t + 4][tid] = p2.y; traj[9 * t + 5][tid] = p2.z;
        traj[9 * t + 6][tid] = p3.x; traj[9 * t + 7][tid] = p3.y; traj[9 * t + 8][tid] = p3.z;
    }

    // Scan inputs must be exact rotations (R6/R8 lesson): GS the endpoint.
    orthonormalize(Fr);

    // ---- Conjugated segment transform: H' = F(end) o F0^-1 ----
    Aff F0i;
    F0i.m[0] = fc.ex[0]; F0i.m[1] = fc.ex[1]; F0i.m[2] = fc.ex[2];
    F0i.m[3] = fc.ey[0]; F0i.m[4] = fc.ey[1]; F0i.m[5] = fc.ey[2];
    F0i.m[6] = fc.ez[0]; F0i.m[7] = fc.ez[1]; F0i.m[8] = fc.ez[2];
    F0i.t[0] = fc.t[0];  F0i.t[1] = fc.t[1];  F0i.t[2] = fc.t[2];

    Aff P = compose(frameToAff(Fr), F0i);

    // Warp inclusive Kogge-Stone scan
#pragma unroll
    for (int off = 1; off < 32; off <<= 1) {
        Aff prev = shflUpAff(P, off);
        Aff comb = compose(prev, P);
        if (lane >= off) P = comb;
    }

    // Publish warp totals
    if (lane == 31 && warp < 3) {
#pragma unroll
        for (int k = 0; k < 9; k++) warpTot[warp][k] = P.m[k];
#pragma unroll
        for (int k = 0; k < 3; k++) warpTot[warp][9 + k] = P.t[k];
    }

    Aff Pex = shflUpAff(P, 1);   // warp-local exclusive prefix
    __syncthreads();

    // W = warpTot[0] o ... o warpTot[warp-1] o Pex   (exclusive prefix = W)
    Aff W = (lane == 0) ? identityAff() : Pex;
    for (int v = warp - 1; v >= 0; v--) {
        Aff T;
#pragma unroll
        for (int k = 0; k < 9; k++) T.m[k] = warpTot[v][k];
#pragma unroll
        for (int k = 0; k < 3; k++) T.t[k] = warpTot[v][9 + k];
        W = compose(T, W);
    }

    // ---- Pass 2: transform local trajectory in SMEM ----
#pragma unroll
    for (int s = 0; s < SEG; s++) {
#pragma unroll
        for (int p = 0; p < 3; p++) {
            V3 v;
            v.x = traj[9 * s + 3 * p + 0][tid];
            v.y = traj[9 * s + 3 * p + 1][tid];
            v.z = traj[9 * s + 3 * p + 2][tid];
            float wx = W.m[0] * v.x + W.m[1] * v.y + W.m[2] * v.z + W.t[0];
            float wy = W.m[3] * v.x + W.m[4] * v.y + W.m[5] * v.z + W.t[1];
            float wz = W.m[6] * v.x + W.m[7] * v.y + W.m[8] * v.z + W.t[2];
            traj[9 * s + 3 * p + 0][tid] = wx;
            traj[9 * s + 3 * p + 1][tid] = wy;
            traj[9 * s + 3 * p + 2][tid] = wz;
        }
    }
    __syncthreads();

    // ---- Writeout: float4 groups, division-free group walk ----
    // float4 index q = it*128 + tid (it = 0..8); floats f = 4q..4q+3,
    // element g = f - 9 lives at traj[g % 36][g / 36].
    // Group advance: g += 512 => ow += 14, rw += 8 (mod 36, one wrap max).
    float* __restrict__ outC = out + (size_t)chain * CHAIN_FLOATS;
    float4* __restrict__ outV = (float4*)outC;
    const float* trajF = &traj[0][0];

    // Iteration 0.
    if (tid < 3) {
        // f = 0..11: init constants (f<9) then owner 0 rows 0..2.
#pragma unroll
        for (int w = 0; w < 4; w++) {
            int f = 4 * tid + w;
            outC[f] = (f < 9) ? c9[f] : trajF[(f - 9) * COLS];
        }
    } else {
        int g0 = 4 * tid - 9;
        int ow0 = g0 / 36;
        int rw0 = g0 - 36 * ow0;
        const float* p0 = trajF + rw0 * COLS + ow0;
        float vv[4];
#pragma unroll
        for (int w = 0; w < 4; w++) {
            const float* a = p0 + w * COLS;
            if (rw0 + w >= ROWS) a -= WRAP;
            vv[w] = *a;
        }
        outV[tid] = make_float4(vv[0], vv[1], vv[2], vv[3]);
    }

    // Iterations 1..8: state computed directly for g1 = 503 + 4*tid.
    int g1 = 503 + 4 * tid;
    int ow = g1 / 36;
    int rw = g1 - 36 * ow;
    const float* p = trajF + rw * COLS + ow;
#pragma unroll
    for (int it = 1; it < 9; it++) {
        float vv[4];
#pragma unroll
        for (int w = 0; w < 4; w++) {
            const float* a = p + w * COLS;
            if (rw + w >= ROWS) a -= WRAP;
            vv[w] = *a;
        }
        outV[it * THREADS + tid] = make_float4(vv[0], vv[1], vv[2], vv[3]);
        rw += 8;
        p += STEP_PTR;
        if (rw >= ROWS) { rw -= ROWS; p -= WRAP; }
    }
}

} // anonymous namespace

extern "C" void kernel_launch(void* const* d_in, const int* in_sizes, int n_in,
                              void* d_out, int out_size) {
    const float* phi   = (const float*)d_in[0];
    const float* psi   = (const float*)d_in[1];
    const float* omega = (const float*)d_in[2];
    const float* bl    = (const float*)d_in[3];
    const float* ba    = (const float*)d_in[4];

    const int B = in_sizes[0] / L_CONST;

    // Canonical frame of (A0, B0, C0) in double precision.
    const double A0[3] = {17.047, 14.099, 3.625};
    const double B0[3] = {16.967, 12.784, 4.338};
    const double C0[3] = {15.685, 12.755, 5.133};
    double ex[3], ab[3], ez[3], ey[3];
    for (int i = 0; i < 3; i++) { ex[i] = C0[i] - B0[i]; ab[i] = B0[i] - A0[i]; }
    double n = sqrt(ex[0]*ex[0] + ex[1]*ex[1] + ex[2]*ex[2]);
    for (int i = 0; i < 3; i++) ex[i] /= n;
    ez[0] = ab[1]*ex[2] - ab[2]*ex[1];
    ez[1] = ab[2]*ex[0] - ab[0]*ex[2];
    ez[2] = ab[0]*ex[1] - ab[1]*ex[0];
    n = sqrt(ez[0]*ez[0] + ez[1]*ez[1] + ez[2]*ez[2]);
    for (int i = 0; i < 3; i++) ez[i] /= n;
    ey[0] = ez[1]*ex[2] - ez[2]*ex[1];
    ey[1] = ez[2]*ex[0] - ez[0]*ex[2];
    ey[2] = ez[0]*ex[1] - ez[1]*ex[0];

    FC fc;
    for (int i = 0; i < 3; i++) {
        fc.ex[i] = (float)ex[i];
        fc.ey[i] = (float)ey[i];
        fc.ez[i] = (float)ez[i];
    }
    fc.t[0] = (float)(-(ex[0]*C0[0] + ex[1]*C0[1] + ex[2]*C0[2]));
    fc.t[1] = (float)(-(ey[0]*C0[0] + ey[1]*C0[1] + ey[2]*C0[2]));
    fc.t[2] = (float)(-(ez[0]*C0[0] + ez[1]*C0[1] + ez[2]*C0[2]));

    nerf_kernel<<<B, THREADS>>>(phi, psi, omega, bl, ba, (float*)d_out, fc);
}